// round 8
// baseline (speedup 1.0000x reference)
#include <cuda_runtime.h>

#define NN 50000
#define NE 800000
#define NG 64

// ---------------- scratch (device globals; no allocation allowed) ----------
__device__ float g_P [NN * 256];   // x @ W1a[0:128,:] + b1a
__device__ float g_T [NN * 256];   // x @ W2a[0:128,:] + b2a
__device__ float g_UG[NG * 256];   // u @ W2a[256:384,:]
__device__ float g_sum[NN * 128];  // scatter-sum of edge MLP output
__device__ int   g_cnt[NN];        // in-degree

// ---------------- packed fp32x2 helpers ------------------------------------
__device__ __forceinline__ unsigned long long ffma2(unsigned long long a,
                                                    unsigned long long b,
                                                    unsigned long long c) {
    unsigned long long d;
    asm("fma.rn.f32x2 %0, %1, %2, %3;" : "=l"(d) : "l"(a), "l"(b), "l"(c));
    return d;
}
__device__ __forceinline__ unsigned long long dup2(float x) {
    unsigned long long d; unsigned int u = __float_as_uint(x);
    asm("mov.b64 %0, {%1, %1};" : "=l"(d) : "r"(u));
    return d;
}
__device__ __forceinline__ float2 ull2f2(unsigned long long v) {
    float2 f;
    f.x = __uint_as_float((unsigned int)(v & 0xFFFFFFFFULL));
    f.y = __uint_as_float((unsigned int)(v >> 32));
    return f;
}

// ---------------- shared-memory layout (floats) -----------------------------
// phase1: sA[64][132] = 8448   | sWc[32][256] = 8192   -> 16640
// phase2: sH1[64][258] = 16512 | sW2[32][128] = 4096   -> 20608  (aliases ph1)
#define SA_STRIDE  132
#define SA_FLOATS  (64 * SA_STRIDE)     // 8448
#define SWC_OFF    SA_FLOATS
#define SH1_STRIDE 258
#define SH1_FLOATS (64 * SH1_STRIDE)    // 16512
#define SW2_OFF    SH1_FLOATS
#define SMEM_FLOATS 20736               // >= 20608, padded
#define SMEM_BYTES  (SMEM_FLOATS * 4)   // 82944 B -> 2 CTAs/SM

// ============================================================================
// phase-1 accumulate over one 32-row K chunk:
// acc[4m][8j] += A[64m x 32k] * Wc[32k x 256n]
// thread (tx,ty): rows ty*4..+3, cols {32j + 2tx, +1}
// ============================================================================
__device__ __forceinline__ void p1_chunk(const float* __restrict__ sA,
                                         const float* __restrict__ sWc,
                                         unsigned long long acc[4][8],
                                         int kb, int tx, int ty) {
#pragma unroll 4
    for (int k2 = 0; k2 < 32; k2++) {
        unsigned long long a2[4];
#pragma unroll
        for (int i = 0; i < 4; i++)
            a2[i] = dup2(sA[(ty * 4 + i) * SA_STRIDE + kb + k2]);
        const float* wr = sWc + k2 * 256 + tx * 2;
#pragma unroll
        for (int j = 0; j < 8; j++) {
            unsigned long long w2 = *(const unsigned long long*)(wr + j * 32);
#pragma unroll
            for (int i = 0; i < 4; i++) acc[i][j] = ffma2(a2[i], w2, acc[i][j]);
        }
    }
}

// ============================================================================
// phase-2 accumulate over one 32-row K chunk:
// acc2[4m][4j] += H1[64m x 32k] * W2c[32k x 128n]
// ============================================================================
__device__ __forceinline__ void p2_chunk(const float* __restrict__ sH1,
                                         const float* __restrict__ sW2,
                                         unsigned long long acc2[4][4],
                                         int kb, int tx, int ty) {
#pragma unroll 4
    for (int k2 = 0; k2 < 32; k2 += 2) {
        unsigned long long alo[4], ahi[4];
#pragma unroll
        for (int i = 0; i < 4; i++) {
            float2 af = *(const float2*)(sH1 + (ty * 4 + i) * SH1_STRIDE + kb + k2);
            alo[i] = dup2(af.x);
            ahi[i] = dup2(af.y);
        }
#pragma unroll
        for (int j = 0; j < 4; j++) {
            unsigned long long wlo = *(const unsigned long long*)(sW2 + k2 * 128 + j * 32 + tx * 2);
            unsigned long long whi = *(const unsigned long long*)(sW2 + (k2 + 1) * 128 + j * 32 + tx * 2);
#pragma unroll
            for (int i = 0; i < 4; i++) {
                acc2[i][j] = ffma2(alo[i], wlo, acc2[i][j]);
                acc2[i][j] = ffma2(ahi[i], whi, acc2[i][j]);
            }
        }
    }
}

// ============================================================================
// Pre-GEMM: out[M,256] = A[M,128] @ W[128,256] (+ bias)
// ============================================================================
__global__ __launch_bounds__(256, 2)
void gemm_k128(const float* __restrict__ A, int M,
               const float* __restrict__ W,
               const float* __restrict__ bias,
               float* __restrict__ out) {
    extern __shared__ float smemf[];
    float* sA  = smemf;
    float* sWc = smemf + SWC_OFF;
    int tid = threadIdx.x;
    int tx = tid & 15, ty = tid >> 4;
    int m0 = blockIdx.x * 64;

    for (int idx = tid; idx < 2048; idx += 256) {
        int m = idx >> 5, kq = idx & 31;
        int gm = m0 + m;
        float4 v = make_float4(0.f, 0.f, 0.f, 0.f);
        if (gm < M) v = ((const float4*)(A + (size_t)gm * 128))[kq];
        *(float4*)(sA + m * SA_STRIDE + kq * 4) = v;
    }

    unsigned long long acc[4][8];
#pragma unroll
    for (int i = 0; i < 4; i++)
#pragma unroll
        for (int j = 0; j < 8; j++) acc[i][j] = 0ULL;

    for (int kb = 0; kb < 128; kb += 32) {
        __syncthreads();
        const float4* wsrc = (const float4*)(W + (size_t)kb * 256);
        for (int idx = tid; idx < 2048; idx += 256)
            ((float4*)sWc)[idx] = wsrc[idx];
        __syncthreads();
        p1_chunk(sA, sWc, acc, kb, tx, ty);
    }

#pragma unroll
    for (int i = 0; i < 4; i++) {
        int gm = m0 + ty * 4 + i;
        if (gm >= M) continue;
        float* orow = out + (size_t)gm * 256;
#pragma unroll
        for (int j = 0; j < 8; j++) {
            int c = j * 32 + tx * 2;
            float2 v = ull2f2(acc[i][j]);
            if (bias) { v.x += bias[c]; v.y += bias[c + 1]; }
            *(float2*)(orow + c) = v;
        }
    }
}

// ============================================================================
// Fused edge kernel: h = relu(EA@W1a_bot + P[row]) @ W1b + b1b ; scatter-add
// 64 edges / block; NE % 64 == 0. edge_index is int32 (JAX x64 disabled).
// ============================================================================
__global__ __launch_bounds__(256, 2)
void edge_kernel(const float* __restrict__ ea,
                 const int* __restrict__ ei,
                 const float* __restrict__ W1a,
                 const float* __restrict__ W1b,
                 const float* __restrict__ b1b) {
    extern __shared__ float smemf[];
    float* sA  = smemf;
    float* sWc = smemf + SWC_OFF;
    int tid = threadIdx.x;
    int tx = tid & 15, ty = tid >> 4;
    int e0 = blockIdx.x * 64;

    const float4* asrc = (const float4*)(ea + (size_t)e0 * 128);
    for (int idx = tid; idx < 2048; idx += 256) {
        int m = idx >> 5, kq = idx & 31;
        *(float4*)(sA + m * SA_STRIDE + kq * 4) = asrc[m * 32 + kq];
    }

    unsigned long long acc[4][8];
#pragma unroll
    for (int i = 0; i < 4; i++)
#pragma unroll
        for (int j = 0; j < 8; j++) acc[i][j] = 0ULL;

    const float* Wb = W1a + 128 * 256;          // bottom (edge_attr) half
    for (int kb = 0; kb < 128; kb += 32) {
        __syncthreads();
        const float4* wsrc = (const float4*)(Wb + (size_t)kb * 256);
        for (int idx = tid; idx < 2048; idx += 256)
            ((float4*)sWc)[idx] = wsrc[idx];
        __syncthreads();
        p1_chunk(sA, sWc, acc, kb, tx, ty);
    }
    __syncthreads();   // everyone done reading sA/sWc before reuse as sH1

    float* sH1 = smemf;
#pragma unroll
    for (int i = 0; i < 4; i++) {
        int e = e0 + ty * 4 + i;
        int r = ei[e];
        const float* Prow = g_P + (size_t)r * 256;
        float* hrow = sH1 + (ty * 4 + i) * SH1_STRIDE;
#pragma unroll
        for (int j = 0; j < 8; j++) {
            int c = j * 32 + tx * 2;
            float2 v = ull2f2(acc[i][j]);
            float2 p = *(const float2*)(Prow + c);
            v.x = fmaxf(v.x + p.x, 0.f);
            v.y = fmaxf(v.y + p.y, 0.f);
            *(float2*)(hrow + c) = v;
        }
    }

    float* sW2 = smemf + SW2_OFF;
    unsigned long long acc2[4][4];
#pragma unroll
    for (int i = 0; i < 4; i++)
#pragma unroll
        for (int j = 0; j < 4; j++) acc2[i][j] = 0ULL;

    for (int kb = 0; kb < 256; kb += 32) {
        __syncthreads();
        const float4* wsrc = (const float4*)(W1b + (size_t)kb * 128);
        for (int idx = tid; idx < 1024; idx += 256)
            ((float4*)sW2)[idx] = wsrc[idx];
        __syncthreads();
        p2_chunk(sH1, sW2, acc2, kb, tx, ty);
    }

#pragma unroll
    for (int i = 0; i < 4; i++) {
        int e = e0 + ty * 4 + i;
        int cd = ei[NE + e];
        float* srow = g_sum + (size_t)cd * 128;
        if (tx == 0) atomicAdd(&g_cnt[cd], 1);
#pragma unroll
        for (int j = 0; j < 4; j++) {
            int c = j * 32 + tx * 2;
            float2 v = ull2f2(acc2[i][j]);
            atomicAdd(srow + c,     v.x + b1b[c]);
            atomicAdd(srow + c + 1, v.y + b1b[c + 1]);
        }
    }
}

// ============================================================================
// Fused node kernel: out = relu(agg@W2a_mid + T + UG[batch]) @ W2b + b2b
// batch is int32.
// ============================================================================
__global__ __launch_bounds__(256, 2)
void node_kernel(const int* __restrict__ batch,
                 const float* __restrict__ W2a,
                 const float* __restrict__ W2b,
                 const float* __restrict__ b2b,
                 float* __restrict__ out) {
    extern __shared__ float smemf[];
    float* sA  = smemf;
    float* sWc = smemf + SWC_OFF;
    int tid = threadIdx.x;
    int tx = tid & 15, ty = tid >> 4;
    int m0 = blockIdx.x * 64;

    for (int idx = tid; idx < 2048; idx += 256) {
        int m = idx >> 5, kq = idx & 31;
        int gm = m0 + m;
        float4 v = make_float4(0.f, 0.f, 0.f, 0.f);
        if (gm < NN) {
            float sc = 1.0f / fmaxf((float)g_cnt[gm], 1.0f);
            float4 s = ((const float4*)(g_sum + (size_t)gm * 128))[kq];
            v.x = s.x * sc; v.y = s.y * sc; v.z = s.z * sc; v.w = s.w * sc;
        }
        *(float4*)(sA + m * SA_STRIDE + kq * 4) = v;
    }

    unsigned long long acc[4][8];
#pragma unroll
    for (int i = 0; i < 4; i++)
#pragma unroll
        for (int j = 0; j < 8; j++) acc[i][j] = 0ULL;

    const float* Wm = W2a + 128 * 256;          // agg rows (128..255)
    for (int kb = 0; kb < 128; kb += 32) {
        __syncthreads();
        const float4* wsrc = (const float4*)(Wm + (size_t)kb * 256);
        for (int idx = tid; idx < 2048; idx += 256)
            ((float4*)sWc)[idx] = wsrc[idx];
        __syncthreads();
        p1_chunk(sA, sWc, acc, kb, tx, ty);
    }
    __syncthreads();

    float* sH1 = smemf;
#pragma unroll
    for (int i = 0; i < 4; i++) {
        int gm = m0 + ty * 4 + i;
        float* hrow = sH1 + (ty * 4 + i) * SH1_STRIDE;
        if (gm < NN) {
            const float* Trow = g_T + (size_t)gm * 256;
            const float* Urow = g_UG + (size_t)batch[gm] * 256;
#pragma unroll
            for (int j = 0; j < 8; j++) {
                int c = j * 32 + tx * 2;
                float2 v = ull2f2(acc[i][j]);
                float2 t = *(const float2*)(Trow + c);
                float2 g = *(const float2*)(Urow + c);
                v.x = fmaxf(v.x + t.x + g.x, 0.f);
                v.y = fmaxf(v.y + t.y + g.y, 0.f);
                *(float2*)(hrow + c) = v;
            }
        } else {
#pragma unroll
            for (int j = 0; j < 8; j++) {
                int c = j * 32 + tx * 2;
                *(float2*)(hrow + c) = make_float2(0.f, 0.f);
            }
        }
    }

    float* sW2 = smemf + SW2_OFF;
    unsigned long long acc2[4][4];
#pragma unroll
    for (int i = 0; i < 4; i++)
#pragma unroll
        for (int j = 0; j < 4; j++) acc2[i][j] = 0ULL;

    for (int kb = 0; kb < 256; kb += 32) {
        __syncthreads();
        const float4* wsrc = (const float4*)(W2b + (size_t)kb * 128);
        for (int idx = tid; idx < 1024; idx += 256)
            ((float4*)sW2)[idx] = wsrc[idx];
        __syncthreads();
        p2_chunk(sH1, sW2, acc2, kb, tx, ty);
    }

#pragma unroll
    for (int i = 0; i < 4; i++) {
        int gm = m0 + ty * 4 + i;
        if (gm >= NN) continue;
        float* orow = out + (size_t)gm * 128;
#pragma unroll
        for (int j = 0; j < 4; j++) {
            int c = j * 32 + tx * 2;
            float2 v = ull2f2(acc2[i][j]);
            v.x += b2b[c];
            v.y += b2b[c + 1];
            *(float2*)(orow + c) = v;
        }
    }
}

// ============================================================================
__global__ void zero_kernel() {
    int idx = blockIdx.x * blockDim.x + threadIdx.x;
    int stride = gridDim.x * blockDim.x;
    float4 z = make_float4(0.f, 0.f, 0.f, 0.f);
    for (int i = idx; i < NN * 32; i += stride) ((float4*)g_sum)[i] = z;
    for (int i = idx; i < NN; i += stride) g_cnt[i] = 0;
}

// ============================================================================
extern "C" void kernel_launch(void* const* d_in, const int* in_sizes, int n_in,
                              void* d_out, int out_size) {
    const float* x     = (const float*)d_in[0];
    const int*   ei    = (const int*)d_in[1];     // int32 (JAX x64 disabled)
    const float* ea    = (const float*)d_in[2];
    const float* u     = (const float*)d_in[3];
    const int*   batch = (const int*)d_in[4];     // int32
    const float* W1a   = (const float*)d_in[5];
    const float* b1a   = (const float*)d_in[6];
    const float* W1b   = (const float*)d_in[7];
    const float* b1b   = (const float*)d_in[8];
    const float* W2a   = (const float*)d_in[9];
    const float* b2a   = (const float*)d_in[10];
    const float* W2b   = (const float*)d_in[11];
    const float* b2b   = (const float*)d_in[12];
    float* out = (float*)d_out;

    cudaFuncSetAttribute(gemm_k128,   cudaFuncAttributeMaxDynamicSharedMemorySize, SMEM_BYTES);
    cudaFuncSetAttribute(edge_kernel, cudaFuncAttributeMaxDynamicSharedMemorySize, SMEM_BYTES);
    cudaFuncSetAttribute(node_kernel, cudaFuncAttributeMaxDynamicSharedMemorySize, SMEM_BYTES);

    void *pP, *pT, *pUG;
    cudaGetSymbolAddress(&pP,  g_P);
    cudaGetSymbolAddress(&pT,  g_T);
    cudaGetSymbolAddress(&pUG, g_UG);

    zero_kernel<<<256, 256>>>();

    // P = x @ W1a[0:128,:] + b1a     [50000, 256]
    gemm_k128<<<(NN + 63) / 64, 256, SMEM_BYTES>>>(x, NN, W1a, b1a, (float*)pP);
    // T = x @ W2a[0:128,:] + b2a     [50000, 256]
    gemm_k128<<<(NN + 63) / 64, 256, SMEM_BYTES>>>(x, NN, W2a, b2a, (float*)pT);
    // UG = u @ W2a[256:384,:]        [64, 256]
    gemm_k128<<<1, 256, SMEM_BYTES>>>(u, NG, W2a + 256 * 256, nullptr, (float*)pUG);

    edge_kernel<<<NE / 64, 256, SMEM_BYTES>>>(ea, ei, W1a, W1b, b1b);

    node_kernel<<<(NN + 63) / 64, 256, SMEM_BYTES>>>(batch, W2a, W2b, b2b, out);
}